// round 1
// baseline (speedup 1.0000x reference)
#include <cuda_runtime.h>
#include <math.h>

// ---------------------------------------------------------------------------
// SwinTransformerBlock  B=2 D=8 H=56 W=56 C=384  heads=12 hd=32 win=(2,7,7)
// N=98 tokens/window, 512 windows, 50176 tokens total, MLP hidden 1536.
// ---------------------------------------------------------------------------

#define NTOK   50176          // B*D*H*W
#define CDIM   384
#define QKVDIM 1152
#define HID    1536
#define NWIN   512
#define NTOKW  98
#define HEADS  12
#define HD     32

// -------------------- scratch (device globals; no allocation) --------------
__device__ float g_xw  [NTOK * CDIM];    // LN1+gathered windows; reused for LN2 out
__device__ float g_qkv [NTOK * QKVDIM];
__device__ float g_attn[NTOK * CDIM];
__device__ float g_xres[NTOK * CDIM];
__device__ float g_h   [NTOK * HID];

// -------------------- row permutation: window token -> spatial row ---------
// For gemm-output row r (= win*98 + n) this returns the spatial row it scatters
// to (reverse window-partition + roll(+1,+3,+3)).  The SAME mapping gives the
// source row for the forward gather (roll(-1,-3,-3) + partition), since the
// roll offsets compose identically.
__device__ __forceinline__ int remap_row(int r) {
    int win = r / NTOKW;
    int n   = r - win * NTOKW;
    int b     = win >> 8;            // 256 windows per sample
    int local = win & 255;
    int dblk = local >> 6;           // 4 d-blocks
    int hblk = (local >> 3) & 7;     // 8 h-blocks
    int wblk = local & 7;            // 8 w-blocks
    int wd  = n / 49;
    int rem = n - wd * 49;
    int wh  = rem / 7;
    int ww  = rem - wh * 7;
    int d = dblk * 2 + wd + 1; if (d >= 8)  d -= 8;
    int h = hblk * 7 + wh + 3; if (h >= 56) h -= 56;
    int w = wblk * 7 + ww + 3; if (w >= 56) w -= 56;
    return ((b * 8 + d) * 56 + h) * 56 + w;
}

// -------------------- LayerNorm (+ optional gather permutation) ------------
template<bool GATHER>
__global__ void __launch_bounds__(128) ln_kernel(
    const float* __restrict__ x, const float* __restrict__ gamma,
    const float* __restrict__ beta, float* __restrict__ out)
{
    int r   = blockIdx.x;
    int src = GATHER ? remap_row(r) : r;
    const float* xp = x + (size_t)src * CDIM;
    int t = threadIdx.x;

    float v0 = xp[t], v1 = xp[t + 128], v2 = xp[t + 256];
    float s  = v0 + v1 + v2;
    float sq = v0 * v0 + v1 * v1 + v2 * v2;

    __shared__ float sb1[4], sb2[4];
    int lane = t & 31, wp = t >> 5;
#pragma unroll
    for (int o = 16; o; o >>= 1) {
        s  += __shfl_xor_sync(0xffffffffu, s,  o);
        sq += __shfl_xor_sync(0xffffffffu, sq, o);
    }
    if (lane == 0) { sb1[wp] = s; sb2[wp] = sq; }
    __syncthreads();
    if (t == 0) {
        sb1[0] = sb1[0] + sb1[1] + sb1[2] + sb1[3];
        sb2[0] = sb2[0] + sb2[1] + sb2[2] + sb2[3];
    }
    __syncthreads();
    float mu   = sb1[0] * (1.0f / CDIM);
    float var  = sb2[0] * (1.0f / CDIM) - mu * mu;
    float rstd = rsqrtf(var + 1e-5f);

    float* op = out + (size_t)r * CDIM;
    op[t]       = (v0 - mu) * rstd * gamma[t]       + beta[t];
    op[t + 128] = (v1 - mu) * rstd * gamma[t + 128] + beta[t + 128];
    op[t + 256] = (v2 - mu) * rstd * gamma[t + 256] + beta[t + 256];
}

// -------------------- fp32 SGEMM 128x128x8, templated epilogue -------------
// EPI 0: C = A*B + bias                                   (qkv)
// EPI 1: xres[remap(row)] = x[remap(row)] + A*B + bias    (proj, scatter)
// EPI 2: C = gelu(A*B + bias)  exact erf                  (fc1)
// EPI 3: C = A*B + bias + add[row]                        (fc2 + residual)
template<int EPI>
__global__ void __launch_bounds__(256) sgemm_k(
    const float* __restrict__ A, const float* __restrict__ B,
    const float* __restrict__ bias, const float* __restrict__ add,
    float* __restrict__ C, int M, int N, int K)
{
    __shared__ float As[8][128];
    __shared__ float Bs[8][128];

    const int tid = threadIdx.x;
    const int m0  = blockIdx.y * 128;
    const int n0  = blockIdx.x * 128;

    const int a_row = tid >> 1;
    const int a_col = (tid & 1) << 2;
    const int b_row = tid >> 5;
    const int b_col = (tid & 31) << 2;

    const float* Aptr = A + (size_t)(m0 + a_row) * K + a_col;
    const float* Bptr = B + (size_t)b_row * N + n0 + b_col;

    const int tr = (tid >> 4) << 3;
    const int tc = (tid & 15) << 3;

    float acc[8][8];
#pragma unroll
    for (int i = 0; i < 8; i++)
#pragma unroll
        for (int j = 0; j < 8; j++) acc[i][j] = 0.0f;

    for (int k0 = 0; k0 < K; k0 += 8) {
        float4 av = *(const float4*)(Aptr + k0);
        As[a_col + 0][a_row] = av.x;
        As[a_col + 1][a_row] = av.y;
        As[a_col + 2][a_row] = av.z;
        As[a_col + 3][a_row] = av.w;
        float4 bv = *(const float4*)(Bptr + (size_t)k0 * N);
        *(float4*)&Bs[b_row][b_col] = bv;
        __syncthreads();
#pragma unroll
        for (int k = 0; k < 8; k++) {
            float4 a0 = *(const float4*)&As[k][tr];
            float4 a1 = *(const float4*)&As[k][tr + 4];
            float4 b0 = *(const float4*)&Bs[k][tc];
            float4 b1 = *(const float4*)&Bs[k][tc + 4];
            float a[8] = {a0.x, a0.y, a0.z, a0.w, a1.x, a1.y, a1.z, a1.w};
            float b[8] = {b0.x, b0.y, b0.z, b0.w, b1.x, b1.y, b1.z, b1.w};
#pragma unroll
            for (int i = 0; i < 8; i++)
#pragma unroll
                for (int j = 0; j < 8; j++) acc[i][j] = fmaf(a[i], b[j], acc[i][j]);
        }
        __syncthreads();
    }

#pragma unroll
    for (int i = 0; i < 8; i++) {
        int row  = m0 + tr + i;
        int trow = (EPI == 1) ? remap_row(row) : row;
#pragma unroll
        for (int j = 0; j < 8; j++) {
            int col = n0 + tc + j;
            float v = acc[i][j] + bias[col];
            if (EPI == 2) v = 0.5f * v * (1.0f + erff(v * 0.70710678118654752f));
            if (EPI == 1) v += add[(size_t)trow * N + col];
            if (EPI == 3) v += add[(size_t)row  * N + col];
            C[(size_t)trow * N + col] = v;
        }
    }
}

// -------------------- windowed attention (one block per window*head) -------
__global__ void __launch_bounds__(128) attn_kernel(
    const float* __restrict__ qkv, const float* __restrict__ mask,
    const float* __restrict__ bias_table, float* __restrict__ out)
{
    __shared__ float q_s [NTOKW * HD];   // q (pre-scaled) [n][d]
    __shared__ float kT_s[HD * NTOKW];   // k transposed   [d][m]
    __shared__ float v_s [NTOKW * HD];   // v              [m][d]
    __shared__ float p_s [4][NTOKW];     // per-warp softmax row

    const int win  = blockIdx.y;
    const int head = blockIdx.x;
    const int tid  = threadIdx.x;

    const float* base = qkv + (size_t)win * NTOKW * QKVDIM + head * HD;
    for (int i = tid; i < NTOKW * HD; i += 128) {
        int m = i >> 5, d = i & 31;
        const float* p = base + (size_t)m * QKVDIM + d;
        q_s[i]           = p[0] * 0.17677669529663687f;   // 1/sqrt(32)
        kT_s[d * NTOKW + m] = p[CDIM];
        v_s[i]           = p[2 * CDIM];
    }
    __syncthreads();

    const int warp = tid >> 5, lane = tid & 31;
    const int local = win & 255;
    const float* maskp = mask + (size_t)local * NTOKW * NTOKW;

    for (int n = warp; n < NTOKW; n += 4) {
        int nd = n / 49, nrem = n - nd * 49;
        int nh = nrem / 7, nw = nrem - nh * 7;

        float qr[HD];
#pragma unroll
        for (int d = 0; d < HD; d++) qr[d] = q_s[n * HD + d];

        float sc[4];
        float mx = -INFINITY;
#pragma unroll
        for (int mi = 0; mi < 4; mi++) {
            int m = lane + mi * 32;
            float s = -INFINITY;
            if (m < NTOKW) {
                float acc = 0.0f;
#pragma unroll
                for (int d = 0; d < HD; d++)
                    acc = fmaf(qr[d], kT_s[d * NTOKW + m], acc);
                int md = m / 49, mrem = m - md * 49;
                int mh = mrem / 7, mw = mrem - mh * 7;
                int ridx = (nd - md + 1) * 169 + (nh - mh + 6) * 13 + (nw - mw + 6);
                acc += bias_table[ridx * HEADS + head] + maskp[n * NTOKW + m];
                s = acc;
            }
            sc[mi] = s;
            mx = fmaxf(mx, s);
        }
#pragma unroll
        for (int o = 16; o; o >>= 1) mx = fmaxf(mx, __shfl_xor_sync(0xffffffffu, mx, o));

        float sum = 0.0f;
#pragma unroll
        for (int mi = 0; mi < 4; mi++) {
            int m = lane + mi * 32;
            if (m < NTOKW) {
                float e = __expf(sc[mi] - mx);
                p_s[warp][m] = e;
                sum += e;
            }
        }
#pragma unroll
        for (int o = 16; o; o >>= 1) sum += __shfl_xor_sync(0xffffffffu, sum, o);
        float inv = 1.0f / sum;
        __syncwarp();

        // out[n][d] for d = lane
        float acc = 0.0f;
        for (int m = 0; m < NTOKW; m++)
            acc = fmaf(p_s[warp][m], v_s[m * HD + lane], acc);
        out[((size_t)win * NTOKW + n) * CDIM + head * HD + lane] = acc * inv;
        __syncwarp();
    }
}

// ---------------------------------------------------------------------------
extern "C" void kernel_launch(void* const* d_in, const int* in_sizes, int n_in,
                              void* d_out, int out_size)
{
    (void)in_sizes; (void)n_in; (void)out_size;
    const float* x          = (const float*)d_in[0];
    const float* mask       = (const float*)d_in[1];
    const float* norm1_g    = (const float*)d_in[2];
    const float* norm1_b    = (const float*)d_in[3];
    const float* qkv_w      = (const float*)d_in[4];
    const float* qkv_b      = (const float*)d_in[5];
    const float* bias_table = (const float*)d_in[6];
    const float* proj_w     = (const float*)d_in[7];
    const float* proj_b     = (const float*)d_in[8];
    const float* norm2_g    = (const float*)d_in[9];
    const float* norm2_b    = (const float*)d_in[10];
    const float* fc1_w      = (const float*)d_in[11];
    const float* fc1_b      = (const float*)d_in[12];
    const float* fc2_w      = (const float*)d_in[13];
    const float* fc2_b      = (const float*)d_in[14];
    float* out = (float*)d_out;

    float *p_xw, *p_qkv, *p_attn, *p_xres, *p_h;
    cudaGetSymbolAddress((void**)&p_xw,   g_xw);
    cudaGetSymbolAddress((void**)&p_qkv,  g_qkv);
    cudaGetSymbolAddress((void**)&p_attn, g_attn);
    cudaGetSymbolAddress((void**)&p_xres, g_xres);
    cudaGetSymbolAddress((void**)&p_h,    g_h);

    // 1. LN1 + roll + window partition (gather)
    ln_kernel<true><<<NTOK, 128>>>(x, norm1_g, norm1_b, p_xw);

    // 2. qkv = xw @ qkv_w + qkv_b            (50176 x 1152, K=384)
    sgemm_k<0><<<dim3(QKVDIM / 128, NTOK / 128), 256>>>(
        p_xw, qkv_w, qkv_b, nullptr, p_qkv, NTOK, QKVDIM, CDIM);

    // 3. windowed attention (bias + mask + softmax + PV)
    attn_kernel<<<dim3(HEADS, NWIN), 128>>>(p_qkv, mask, bias_table, p_attn);

    // 4. proj + window-reverse + roll-back scatter + shortcut -> xres
    sgemm_k<1><<<dim3(CDIM / 128, NTOK / 128), 256>>>(
        p_attn, proj_w, proj_b, x, p_xres, NTOK, CDIM, CDIM);

    // 5. LN2 (rows identity) -> reuse g_xw
    ln_kernel<false><<<NTOK, 128>>>(p_xres, norm2_g, norm2_b, p_xw);

    // 6. fc1 + exact GELU                    (50176 x 1536, K=384)
    sgemm_k<2><<<dim3(HID / 128, NTOK / 128), 256>>>(
        p_xw, fc1_w, fc1_b, nullptr, p_h, NTOK, HID, CDIM);

    // 7. fc2 + bias + residual -> d_out      (50176 x 384, K=1536)
    sgemm_k<3><<<dim3(CDIM / 128, NTOK / 128), 256>>>(
        p_h, fc2_w, fc2_b, p_xres, out, NTOK, CDIM, HID);
}

// round 3
// speedup vs baseline: 2.1296x; 2.1296x over previous
#include <cuda_runtime.h>
#include <math.h>
#include <stdint.h>

// ---------------------------------------------------------------------------
// SwinTransformerBlock  B=2 D=8 H=56 W=56 C=384  heads=12 hd=32 win=(2,7,7)
// GEMMs on mma.sync.m16n8k8 tf32 (compute_103 baseline ISA; tcgen05 is not
// available because the harness compiles PTX for non-'a' sm_103).
// ---------------------------------------------------------------------------

#define NTOK   50176
#define CDIM   384
#define QKVDIM 1152
#define HID    1536
#define NWIN   512
#define NTOKW  98
#define HEADS  12
#define HD     32

// -------------------- scratch (device globals; no allocation) --------------
__device__ float g_xw  [NTOK * CDIM];
__device__ float g_qkv [NTOK * QKVDIM];
__device__ float g_attn[NTOK * CDIM];
__device__ float g_xres[NTOK * CDIM];
__device__ float g_h   [NTOK * HID];
#define WT_QKV 0
#define WT_PROJ (CDIM * QKVDIM)
#define WT_FC1  (WT_PROJ + CDIM * CDIM)
#define WT_FC2  (WT_FC1 + CDIM * HID)
__device__ float g_wt[CDIM*QKVDIM + CDIM*CDIM + CDIM*HID + HID*CDIM];

// -------------------- helpers ----------------------------------------------
__device__ __forceinline__ uint32_t smem_u32(const void* p) {
    uint32_t a;
    asm("{ .reg .u64 t; cvta.to.shared.u64 t, %1; cvt.u32.u64 %0, t; }" : "=r"(a) : "l"(p));
    return a;
}
__device__ __forceinline__ uint32_t f2tf(float x) {
    uint32_t u; asm("cvt.rna.tf32.f32 %0, %1;" : "=r"(u) : "f"(x));
    return u;
}
__device__ __forceinline__ float rna_tf32(float x) { return __uint_as_float(f2tf(x)); }

__device__ __forceinline__ void cp_async16(uint32_t dst, const void* src) {
    asm volatile("cp.async.ca.shared.global [%0], [%1], 16;" :: "r"(dst), "l"(src));
}
__device__ __forceinline__ void mma1688(float* c, const uint32_t* a, const uint32_t* b) {
    asm volatile("mma.sync.aligned.m16n8k8.row.col.f32.tf32.tf32.f32 "
        "{%0,%1,%2,%3}, {%4,%5,%6,%7}, {%8,%9}, {%0,%1,%2,%3};"
        : "+f"(c[0]), "+f"(c[1]), "+f"(c[2]), "+f"(c[3])
        : "r"(a[0]), "r"(a[1]), "r"(a[2]), "r"(a[3]), "r"(b[0]), "r"(b[1]));
}

// -------------------- row permutation (window <-> spatial) -----------------
__device__ __forceinline__ int remap_row(int r) {
    int win = r / NTOKW;
    int n   = r - win * NTOKW;
    int b     = win >> 8;
    int local = win & 255;
    int dblk = local >> 6, hblk = (local >> 3) & 7, wblk = local & 7;
    int wd  = n / 49;
    int rem = n - wd * 49;
    int wh  = rem / 7, ww = rem - wh * 7;
    int d = dblk * 2 + wd + 1; if (d >= 8)  d -= 8;
    int h = hblk * 7 + wh + 3; if (h >= 56) h -= 56;
    int w = wblk * 7 + ww + 3; if (w >= 56) w -= 56;
    return ((b * 8 + d) * 56 + h) * 56 + w;
}

// -------------------- LayerNorm (+ optional gather) ------------------------
template<bool GATHER>
__global__ void __launch_bounds__(128) ln_kernel(
    const float* __restrict__ x, const float* __restrict__ gamma,
    const float* __restrict__ beta, float* __restrict__ out)
{
    int r   = blockIdx.x;
    int src = GATHER ? remap_row(r) : r;
    const float* xp = x + (size_t)src * CDIM;
    int t = threadIdx.x;

    float v0 = xp[t], v1 = xp[t + 128], v2 = xp[t + 256];
    float s  = v0 + v1 + v2;
    float sq = v0 * v0 + v1 * v1 + v2 * v2;

    __shared__ float sb1[4], sb2[4];
    int lane = t & 31, wp = t >> 5;
#pragma unroll
    for (int o = 16; o; o >>= 1) {
        s  += __shfl_xor_sync(0xffffffffu, s,  o);
        sq += __shfl_xor_sync(0xffffffffu, sq, o);
    }
    if (lane == 0) { sb1[wp] = s; sb2[wp] = sq; }
    __syncthreads();
    if (t == 0) {
        sb1[0] = sb1[0] + sb1[1] + sb1[2] + sb1[3];
        sb2[0] = sb2[0] + sb2[1] + sb2[2] + sb2[3];
    }
    __syncthreads();
    float mu   = sb1[0] * (1.0f / CDIM);
    float var  = sb2[0] * (1.0f / CDIM) - mu * mu;
    float rstd = rsqrtf(var + 1e-5f);

    float* op = out + (size_t)r * CDIM;
    op[t]       = (v0 - mu) * rstd * gamma[t]       + beta[t];
    op[t + 128] = (v1 - mu) * rstd * gamma[t + 128] + beta[t + 128];
    op[t + 256] = (v2 - mu) * rstd * gamma[t + 256] + beta[t + 256];
}

// -------------------- weight transpose + tf32 round:  W[K,N] -> WT[N,K] ----
__global__ void transpose_rna(const float* __restrict__ W, float* __restrict__ WT,
                              int K, int N)
{
    __shared__ float tile[32][33];
    int kb = blockIdx.y * 32, nb = blockIdx.x * 32;
    int tx = threadIdx.x, ty = threadIdx.y;
#pragma unroll
    for (int j = ty; j < 32; j += 8)
        tile[j][tx] = rna_tf32(W[(size_t)(kb + j) * N + nb + tx]);
    __syncthreads();
#pragma unroll
    for (int j = ty; j < 32; j += 8)
        WT[(size_t)(nb + j) * K + kb + tx] = tile[tx][j];
}

// -------------------- tf32 mma.sync GEMM  BM=BN=128, BK=16, 4 stages -------
// A: [M,K] activations (row-major, fp32, rounded in-reg)
// WT: [N,K] pre-rounded weights (row-major)
// EPI 0: C = A*WT^T + bias
// EPI 1: C[remap(row)] = add[remap(row)] + .. + bias
// EPI 2: C = gelu(.. + bias)
// EPI 3: C = .. + bias + add[row]
#define BK 16
#define KST 20          // smem row stride in floats (BK + 4): conflict-free
#define STG 4
#define STAGE_F (128 * KST)            // floats per operand per stage
#define GSMEM_BYTES (2 * STG * STAGE_F * 4)   // 81920

template<int EPI>
__global__ void __launch_bounds__(256, 2) mma_gemm(
    const float* __restrict__ A, const float* __restrict__ WT,
    const float* __restrict__ bias, const float* __restrict__ add,
    float* __restrict__ C, int M, int N, int K)
{
    extern __shared__ float smem[];
    float* sA = smem;
    float* sB = smem + STG * STAGE_F;

    const int tid = threadIdx.x, lane = tid & 31, wid = tid >> 5;
    const int m0 = blockIdx.y * 128, n0 = blockIdx.x * 128;
    const int wm = (wid & 1) * 64, wn = (wid >> 1) * 32;

    const uint32_t sAu = smem_u32(sA), sBu = smem_u32(sB);

    const int row = tid >> 2, ch4 = (tid & 3) * 4;
    const float* Agp = A  + (size_t)(m0 + row) * K + ch4;
    const float* Bgp = WT + (size_t)(n0 + row) * K + ch4;
    const uint32_t dOffA = (uint32_t)(row * KST + ch4) * 4;
    const int nk = K / BK;

    float acc[16][4];
#pragma unroll
    for (int i = 0; i < 16; i++)
#pragma unroll
        for (int j = 0; j < 4; j++) acc[i][j] = 0.0f;

#define STAGE_LOAD(slot, ks) do { \
        uint32_t _da = sAu + (uint32_t)(slot) * (STAGE_F * 4) + dOffA; \
        uint32_t _db = sBu + (uint32_t)(slot) * (STAGE_F * 4) + dOffA; \
        const float* _ga = Agp + (ks) * BK; \
        const float* _gb = Bgp + (ks) * BK; \
        cp_async16(_da, _ga); \
        cp_async16(_da + 64 * KST * 4, _ga + (size_t)64 * K); \
        cp_async16(_db, _gb); \
        cp_async16(_db + 64 * KST * 4, _gb + (size_t)64 * K); \
    } while (0)

#pragma unroll
    for (int s = 0; s < STG - 1; s++) {
        if (s < nk) STAGE_LOAD(s, s);
        asm volatile("cp.async.commit_group;");
    }

    const int g = lane >> 2, j = lane & 3;

    for (int ks = 0; ks < nk; ks++) {
        int pf = ks + STG - 1;
        if (pf < nk) STAGE_LOAD(pf % STG, pf);
        asm volatile("cp.async.commit_group;");
        asm volatile("cp.async.wait_group %0;" :: "n"(STG - 1));
        __syncthreads();

        const float* As_p = sA + (ks % STG) * STAGE_F;
        const float* Bs_p = sB + (ks % STG) * STAGE_F;
#pragma unroll
        for (int kk = 0; kk < 2; kk++) {
            uint32_t af[4][4], bf[4][2];
            const int cb = kk * 8 + j;
#pragma unroll
            for (int mt = 0; mt < 4; mt++) {
                int rb = wm + mt * 16 + g;
                af[mt][0] = f2tf(As_p[rb * KST + cb]);
                af[mt][1] = f2tf(As_p[(rb + 8) * KST + cb]);
                af[mt][2] = f2tf(As_p[rb * KST + cb + 4]);
                af[mt][3] = f2tf(As_p[(rb + 8) * KST + cb + 4]);
            }
#pragma unroll
            for (int nt = 0; nt < 4; nt++) {
                int nb = wn + nt * 8 + g;
                bf[nt][0] = __float_as_uint(Bs_p[nb * KST + cb]);
                bf[nt][1] = __float_as_uint(Bs_p[nb * KST + cb + 4]);
            }
#pragma unroll
            for (int mt = 0; mt < 4; mt++)
#pragma unroll
                for (int nt = 0; nt < 4; nt++)
                    mma1688(acc[mt * 4 + nt], af[mt], bf[nt]);
        }
        __syncthreads();
    }

    // ---- epilogue ----
    const int j2 = (lane & 3) * 2;
#pragma unroll
    for (int mt = 0; mt < 4; mt++) {
        int r_lo = m0 + wm + mt * 16 + g;
        int r_hi = r_lo + 8;
        int t_lo = (EPI == 1) ? remap_row(r_lo) : r_lo;
        int t_hi = (EPI == 1) ? remap_row(r_hi) : r_hi;
#pragma unroll
        for (int nt = 0; nt < 4; nt++) {
            int c = n0 + wn + nt * 8 + j2;
            float2 bv = *(const float2*)(bias + c);
            const float* a = acc[mt * 4 + nt];
            float x0 = a[0] + bv.x, x1 = a[1] + bv.y;
            float x2 = a[2] + bv.x, x3 = a[3] + bv.y;
            if (EPI == 2) {
                x0 = 0.5f * x0 * (1.0f + erff(x0 * 0.70710678118654752f));
                x1 = 0.5f * x1 * (1.0f + erff(x1 * 0.70710678118654752f));
                x2 = 0.5f * x2 * (1.0f + erff(x2 * 0.70710678118654752f));
                x3 = 0.5f * x3 * (1.0f + erff(x3 * 0.70710678118654752f));
            }
            if (EPI == 1 || EPI == 3) {
                float2 alo = *(const float2*)(add + (size_t)t_lo * N + c);
                float2 ahi = *(const float2*)(add + (size_t)t_hi * N + c);
                x0 += alo.x; x1 += alo.y; x2 += ahi.x; x3 += ahi.y;
            }
            *(float2*)(C + (size_t)t_lo * N + c) = make_float2(x0, x1);
            *(float2*)(C + (size_t)t_hi * N + c) = make_float2(x2, x3);
        }
    }
}

// -------------------- windowed attention (one block per window*head) -------
__global__ void __launch_bounds__(128) attn_kernel(
    const float* __restrict__ qkv, const float* __restrict__ mask,
    const float* __restrict__ bias_table, float* __restrict__ out)
{
    __shared__ float q_s [NTOKW * HD];
    __shared__ float kT_s[HD * NTOKW];
    __shared__ float v_s [NTOKW * HD];
    __shared__ float p_s [4][NTOKW];

    const int win  = blockIdx.y;
    const int head = blockIdx.x;
    const int tid  = threadIdx.x;

    const float* base = qkv + (size_t)win * NTOKW * QKVDIM + head * HD;
    for (int i = tid; i < NTOKW * HD; i += 128) {
        int m = i >> 5, d = i & 31;
        const float* p = base + (size_t)m * QKVDIM + d;
        q_s[i]              = p[0] * 0.17677669529663687f;
        kT_s[d * NTOKW + m] = p[CDIM];
        v_s[i]              = p[2 * CDIM];
    }
    __syncthreads();

    const int warp = tid >> 5, lane = tid & 31;
    const int local = win & 255;
    const float* maskp = mask + (size_t)local * NTOKW * NTOKW;

    for (int n = warp; n < NTOKW; n += 4) {
        int nd = n / 49, nrem = n - nd * 49;
        int nh = nrem / 7, nw = nrem - nh * 7;

        float qr[HD];
#pragma unroll
        for (int d = 0; d < HD; d++) qr[d] = q_s[n * HD + d];

        float sc[4];
        float mx = -INFINITY;
#pragma unroll
        for (int mi = 0; mi < 4; mi++) {
            int m = lane + mi * 32;
            float s = -INFINITY;
            if (m < NTOKW) {
                float acc = 0.0f;
#pragma unroll
                for (int d = 0; d < HD; d++)
                    acc = fmaf(qr[d], kT_s[d * NTOKW + m], acc);
                int md = m / 49, mrem = m - md * 49;
                int mh = mrem / 7, mw = mrem - mh * 7;
                int ridx = (nd - md + 1) * 169 + (nh - mh + 6) * 13 + (nw - mw + 6);
                acc += bias_table[ridx * HEADS + head] + maskp[n * NTOKW + m];
                s = acc;
            }
            sc[mi] = s;
            mx = fmaxf(mx, s);
        }
#pragma unroll
        for (int o = 16; o; o >>= 1) mx = fmaxf(mx, __shfl_xor_sync(0xffffffffu, mx, o));

        float sum = 0.0f;
#pragma unroll
        for (int mi = 0; mi < 4; mi++) {
            int m = lane + mi * 32;
            if (m < NTOKW) {
                float e = __expf(sc[mi] - mx);
                p_s[warp][m] = e;
                sum += e;
            }
        }
#pragma unroll
        for (int o = 16; o; o >>= 1) sum += __shfl_xor_sync(0xffffffffu, sum, o);
        float inv = 1.0f / sum;
        __syncwarp();

        float acc = 0.0f;
        for (int m = 0; m < NTOKW; m++)
            acc = fmaf(p_s[warp][m], v_s[m * HD + lane], acc);
        out[((size_t)win * NTOKW + n) * CDIM + head * HD + lane] = acc * inv;
        __syncwarp();
    }
}

// ---------------------------------------------------------------------------
extern "C" void kernel_launch(void* const* d_in, const int* in_sizes, int n_in,
                              void* d_out, int out_size)
{
    (void)in_sizes; (void)n_in; (void)out_size;
    const float* x          = (const float*)d_in[0];
    const float* mask       = (const float*)d_in[1];
    const float* norm1_g    = (const float*)d_in[2];
    const float* norm1_b    = (const float*)d_in[3];
    const float* qkv_w      = (const float*)d_in[4];
    const float* qkv_b      = (const float*)d_in[5];
    const float* bias_table = (const float*)d_in[6];
    const float* proj_w     = (const float*)d_in[7];
    const float* proj_b     = (const float*)d_in[8];
    const float* norm2_g    = (const float*)d_in[9];
    const float* norm2_b    = (const float*)d_in[10];
    const float* fc1_w      = (const float*)d_in[11];
    const float* fc1_b      = (const float*)d_in[12];
    const float* fc2_w      = (const float*)d_in[13];
    const float* fc2_b      = (const float*)d_in[14];
    float* out = (float*)d_out;

    float *p_xw, *p_qkv, *p_attn, *p_xres, *p_h, *p_wt;
    cudaGetSymbolAddress((void**)&p_xw,   g_xw);
    cudaGetSymbolAddress((void**)&p_qkv,  g_qkv);
    cudaGetSymbolAddress((void**)&p_attn, g_attn);
    cudaGetSymbolAddress((void**)&p_xres, g_xres);
    cudaGetSymbolAddress((void**)&p_h,    g_h);
    cudaGetSymbolAddress((void**)&p_wt,   g_wt);

    cudaFuncSetAttribute(mma_gemm<0>, cudaFuncAttributeMaxDynamicSharedMemorySize, GSMEM_BYTES);
    cudaFuncSetAttribute(mma_gemm<1>, cudaFuncAttributeMaxDynamicSharedMemorySize, GSMEM_BYTES);
    cudaFuncSetAttribute(mma_gemm<2>, cudaFuncAttributeMaxDynamicSharedMemorySize, GSMEM_BYTES);
    cudaFuncSetAttribute(mma_gemm<3>, cudaFuncAttributeMaxDynamicSharedMemorySize, GSMEM_BYTES);

    dim3 tb(32, 8);
    transpose_rna<<<dim3(QKVDIM/32, CDIM/32), tb>>>(qkv_w,  p_wt + WT_QKV,  CDIM, QKVDIM);
    transpose_rna<<<dim3(CDIM/32,  CDIM/32), tb>>>(proj_w, p_wt + WT_PROJ, CDIM, CDIM);
    transpose_rna<<<dim3(HID/32,   CDIM/32), tb>>>(fc1_w,  p_wt + WT_FC1,  CDIM, HID);
    transpose_rna<<<dim3(CDIM/32,  HID/32),  tb>>>(fc2_w,  p_wt + WT_FC2,  HID,  CDIM);

    // 1. LN1 + roll + window partition (gather)
    ln_kernel<true><<<NTOK, 128>>>(x, norm1_g, norm1_b, p_xw);

    // 2. qkv
    mma_gemm<0><<<dim3(QKVDIM/128, NTOK/128), 256, GSMEM_BYTES>>>(
        p_xw, p_wt + WT_QKV, qkv_b, nullptr, p_qkv, NTOK, QKVDIM, CDIM);

    // 3. windowed attention
    attn_kernel<<<dim3(HEADS, NWIN), 128>>>(p_qkv, mask, bias_table, p_attn);

    // 4. proj + scatter + shortcut
    mma_gemm<1><<<dim3(CDIM/128, NTOK/128), 256, GSMEM_BYTES>>>(
        p_attn, p_wt + WT_PROJ, proj_b, x, p_xres, NTOK, CDIM, CDIM);

    // 5. LN2
    ln_kernel<false><<<NTOK, 128>>>(p_xres, norm2_g, norm2_b, p_xw);

    // 6. fc1 + GELU
    mma_gemm<2><<<dim3(HID/128, NTOK/128), 256, GSMEM_BYTES>>>(
        p_xw, p_wt + WT_FC1, fc1_b, nullptr, p_h, NTOK, HID, CDIM);

    // 7. fc2 + residual -> out
    mma_gemm<3><<<dim3(CDIM/128, NTOK/128), 256, GSMEM_BYTES>>>(
        p_h, p_wt + WT_FC2, fc2_b, p_xres, out, NTOK, CDIM, HID);
}